// round 12
// baseline (speedup 1.0000x reference)
#include <cuda_runtime.h>
#include <cuda_fp16.h>
#include <cstdint>
#include <math.h>

#define DIM 128
#define TILE 128
#define BMAX 8192
#define NTMAX 64
#define TPB 4                  // B-tiles per CTA; A tile stays resident
#define LDW 52                 // main-tile smem row stride in words (208B), conflict-free

// smem word offsets
#define A_W      (128 * LDW)                 // 6656
#define B_W      (128 * LDW)                 // 6656
#define ADUP_OFF (A_W + 2 * B_W)             // 19968 (128 rows x 36 w)
#define BP_W     (64 * 36)                   // 2304
#define BP_OFF   (ADUP_OFF + 128 * 36)       // 24576 (2 buffers)
#define NORM_OFF (BP_OFF + 2 * BP_W)         // 29184 (512 floats)
#define SMEM_WORDS (NORM_OFF + 512)          // 29696 -> 118784 bytes

__device__ float g_nsk[BMAX];
__device__ float g_nim[BMAX];
__device__ uint32_t g_skh[BMAX * 64];        // f16x2-packed sk rows (full K)
__device__ uint32_t g_imh[BMAX * 64];        // f16x2-packed im rows (full K)
__device__ uint32_t g_skdup[BMAX * 32];      // k in [96,128): (a,a) duplicated f16x2
__device__ uint32_t g_impair[(BMAX / 2) * 32]; // k in [96,128): (im[2p],im[2p+1]) f16x2
__device__ float g_partial[(size_t)BMAX * NTMAX * 2];
__device__ float g_diag[BMAX];
__device__ float g_bsum[32];

static __device__ __forceinline__ uint32_t s2u(const void* p) {
    uint32_t a;
    asm("{ .reg .u64 t; cvta.to.shared.u64 t, %1; cvt.u32.u64 %0, t; }" : "=r"(a) : "l"(p));
    return a;
}
static __device__ __forceinline__ void cpa16(uint32_t dst, const void* src) {
    asm volatile("cp.async.cg.shared.global [%0], [%1], 16;" :: "r"(dst), "l"(src) : "memory");
}
#define CP_COMMIT() asm volatile("cp.async.commit_group;" ::: "memory")
#define CP_WAIT0()  asm volatile("cp.async.wait_group 0;" ::: "memory")
#define CP_WAIT1()  asm volatile("cp.async.wait_group 1;" ::: "memory")

static __device__ __forceinline__ void mma16h(uint32_t* c, const uint32_t* a, const uint32_t* b) {
    asm("mma.sync.aligned.m16n8k16.row.col.f16.f16.f16.f16 "
        "{%0,%1}, {%2,%3,%4,%5}, {%6,%7}, {%0,%1};"
        : "+r"(c[0]), "+r"(c[1])
        : "r"(a[0]), "r"(a[1]), "r"(a[2]), "r"(a[3]), "r"(b[0]), "r"(b[1]));
}
static __device__ __forceinline__ void hfma2(uint32_t& c, uint32_t a, uint32_t b) {
    asm("fma.rn.f16x2 %0, %1, %2, %0;" : "+r"(c) : "r"(a), "r"(b));
}

// ---------------------------------------------------------------------------
// prep: y=0 sk norms+pack+dup; y=1 im norms+pack; y=2 exact diag; y=3 im pairs
// ---------------------------------------------------------------------------
__global__ void prep_kernel(const float* __restrict__ sk,
                            const float* __restrict__ im, int B) {
    int row = (blockIdx.x * blockDim.x + threadIdx.x) >> 5;
    int lane = threadIdx.x & 31;
    if (row >= B) return;
    if (blockIdx.y < 2) {
        const float* src = blockIdx.y ? im : sk;
        float* ndst = blockIdx.y ? g_nim : g_nsk;
        uint32_t* bdst = blockIdx.y ? g_imh : g_skh;
        float4 v = ((const float4*)(src + (size_t)row * DIM))[lane];
        __half2 h0 = __floats2half2_rn(v.x, v.y);
        __half2 h1 = __floats2half2_rn(v.z, v.w);
        bdst[row * 64 + lane * 2]     = *(uint32_t*)&h0;
        bdst[row * 64 + lane * 2 + 1] = *(uint32_t*)&h1;
        if (blockIdx.y == 0 && lane >= 24) {        // k in [96,128): duplicated
            int j0 = lane * 4 - 96;
            __half2 d0 = __floats2half2_rn(v.x, v.x);
            __half2 d1 = __floats2half2_rn(v.y, v.y);
            __half2 d2 = __floats2half2_rn(v.z, v.z);
            __half2 d3 = __floats2half2_rn(v.w, v.w);
            g_skdup[row * 32 + j0 + 0] = *(uint32_t*)&d0;
            g_skdup[row * 32 + j0 + 1] = *(uint32_t*)&d1;
            g_skdup[row * 32 + j0 + 2] = *(uint32_t*)&d2;
            g_skdup[row * 32 + j0 + 3] = *(uint32_t*)&d3;
        }
        float s = v.x * v.x + v.y * v.y + v.z * v.z + v.w * v.w;
#pragma unroll
        for (int o = 16; o; o >>= 1) s += __shfl_xor_sync(0xffffffffu, s, o);
        if (lane == 0) ndst[row] = s;
    } else if (blockIdx.y == 2) {
        float4 a = ((const float4*)(sk + (size_t)row * DIM))[lane];
        float4 b = ((const float4*)(im + (size_t)row * DIM))[lane];
        float dx = a.x - b.x, dy = a.y - b.y, dz = a.z - b.z, dw = a.w - b.w;
        float s = dx * dx + dy * dy + dz * dz + dw * dw;
#pragma unroll
        for (int o = 16; o; o >>= 1) s += __shfl_xor_sync(0xffffffffu, s, o);
        if (lane == 0) g_diag[row] = sqrtf(s);
    } else {
        int p = row;                                 // pair index
        if (p >= B / 2) return;
        float a = im[(size_t)(2 * p) * DIM + 96 + lane];
        float b = im[(size_t)(2 * p + 1) * DIM + 96 + lane];
        __half2 h = __floats2half2_rn(a, b);         // lo = even col
        g_impair[p * 32 + lane] = *(uint32_t*)&h;
    }
}

// ---------------------------------------------------------------------------
// Hybrid: f16-acc MMA (k<96, tensor pipe) + HFMA2 (k in [96,128), fma pipe)
// accumulating into the SAME packed f16x2 accs; epilogue of tile t-1
// interleaved per k-step (R5 structure). 8 warps, warp tile 32x64.
// ---------------------------------------------------------------------------
__global__ void __launch_bounds__(256, 1)
dist_mma(int nt) {
    extern __shared__ uint32_t smw[];
    const uint32_t sbase = s2u(smw);
    uint32_t* As = smw;
    float* nsm = (float*)(smw + NORM_OFF);

    const int tid = threadIdx.x;
    const int wid = tid >> 5;
    const int lane = tid & 31;
    const int g = lane >> 2;
    const int t = lane & 3;
    const int wm = wid & 3;
    const int wn = wid >> 2;

    const int ntg = nt / TPB;
    const int bm = blockIdx.x / ntg;
    const int bn0 = (blockIdx.x % ntg) * TPB;

    // ---- prologue ----
    {
        const uint32_t* Ag = g_skh + (size_t)bm * TILE * 64;
        const uint32_t* Bg = g_imh + (size_t)bn0 * TILE * 64;
#pragma unroll
        for (int it = 0; it < 6; it++) {             // A + B0: 12 chunks x 128 rows (k<96)
            int c = it * 256 + tid;
            int ch = c >> 7, row = c & 127;
            cpa16(sbase + ((uint32_t)row * LDW + ch * 4) * 4, Ag + row * 64 + ch * 4);
            cpa16(sbase + (B_W * 0 + A_W + (uint32_t)row * LDW + ch * 4) * 4, Bg + row * 64 + ch * 4);
        }
#pragma unroll
        for (int it = 0; it < 4; it++) {             // A-dup: 8 chunks x 128 rows
            int c = it * 256 + tid;
            int ch = c >> 7, row = c & 127;
            cpa16(sbase + (ADUP_OFF + (uint32_t)row * 36 + ch * 4) * 4,
                  g_skdup + (size_t)(bm * TILE + row) * 32 + ch * 4);
        }
#pragma unroll
        for (int it = 0; it < 2; it++) {             // B-pair0: 8 chunks x 64 pairs
            int c = it * 256 + tid;
            int ch = c >> 6, p = c & 63;
            cpa16(sbase + (BP_OFF + (uint32_t)p * 36 + ch * 4) * 4,
                  g_impair + (size_t)(bn0 * 64 + p) * 32 + ch * 4);
        }
        if (tid < 128)                               // 4 tiles' norms
            cpa16(sbase + NORM_OFF * 4 + (uint32_t)tid * 16, g_nim + (size_t)bn0 * TILE + tid * 4);
        CP_COMMIT();
        const uint32_t* Bg1 = g_imh + (size_t)(bn0 + 1) * TILE * 64;
#pragma unroll
        for (int it = 0; it < 6; it++) {
            int c = it * 256 + tid;
            int ch = c >> 7, row = c & 127;
            cpa16(sbase + (A_W + B_W + (uint32_t)row * LDW + ch * 4) * 4, Bg1 + row * 64 + ch * 4);
        }
#pragma unroll
        for (int it = 0; it < 2; it++) {
            int c = it * 256 + tid;
            int ch = c >> 6, p = c & 63;
            cpa16(sbase + (BP_OFF + BP_W + (uint32_t)p * 36 + ch * 4) * 4,
                  g_impair + (size_t)((bn0 + 1) * 64 + p) * 32 + ch * 4);
        }
        CP_COMMIT();
        CP_WAIT1();
    }
    __syncthreads();

    float nr[2][2];
#pragma unroll
    for (int mt = 0; mt < 2; mt++)
#pragma unroll
        for (int h = 0; h < 2; h++)
            nr[mt][h] = g_nsk[bm * TILE + wm * 32 + mt * 16 + h * 8 + g];

    const int a_base = (wm * 32 + g) * LDW + t;
    const int b_base = (wn * 64 + g) * LDW + t;

    uint32_t acc[2][2][8][2];      // [buf][mt][nb][h]  packed f16x2
    uint32_t adup[4][8];           // duplicated A slice for current k-chunk
    float rs[2][2];

#pragma unroll
    for (int tt = 0; tt <= TPB; tt++) {
        const bool do_main = (tt < TPB);
        const bool do_epi = (tt > 0);
        const int nbuf = tt & 1;
        const int bn_old = bn0 + tt - 1;

        if (tt + 1 < TPB) {
            const uint32_t* Bg = g_imh + (size_t)(bn0 + tt + 1) * TILE * 64;
            uint32_t dbuf = sbase + (A_W + ((tt + 1) & 1) * B_W) * 4;
#pragma unroll
            for (int it = 0; it < 6; it++) {
                int c = it * 256 + tid;
                int ch = c >> 7, row = c & 127;
                cpa16(dbuf + ((uint32_t)row * LDW + ch * 4) * 4, Bg + row * 64 + ch * 4);
            }
            uint32_t pbuf = sbase + (BP_OFF + ((tt + 1) & 1) * BP_W) * 4;
#pragma unroll
            for (int it = 0; it < 2; it++) {
                int c = it * 256 + tid;
                int ch = c >> 6, p = c & 63;
                cpa16(pbuf + ((uint32_t)p * 36 + ch * 4) * 4,
                      g_impair + (size_t)((bn0 + tt + 1) * 64 + p) * 32 + ch * 4);
            }
            CP_COMMIT();
        }

        uint32_t (*accN)[8][2] = acc[nbuf];
        uint32_t (*accO)[8][2] = acc[nbuf ^ 1];
        const uint32_t* Bs = smw + A_W + (tt & 1) * B_W;
        const uint32_t bp_off = BP_OFF + (tt & 1) * BP_W;

        if (do_main) {
#pragma unroll
            for (int mt = 0; mt < 2; mt++)
#pragma unroll
                for (int nb = 0; nb < 8; nb++) {
                    accN[mt][nb][0] = 0u;
                    accN[mt][nb][1] = 0u;
                }
        }
        if (do_epi) { rs[0][0] = rs[0][1] = rs[1][0] = rs[1][1] = 0.f; }

        // 8 slots: MMA kstep (ks<6) + HFMA2 sub-chunk + epilogue chunk
#pragma unroll
        for (int ks = 0; ks < 8; ks++) {
            if (do_main && ks < 6) {
                const int ko = ks * 8;
                uint32_t a[2][4], b[8][2];
#pragma unroll
                for (int mt = 0; mt < 2; mt++) {
                    int ba = a_base + mt * 16 * LDW + ko;
                    a[mt][0] = As[ba];
                    a[mt][1] = As[ba + 8 * LDW];
                    a[mt][2] = As[ba + 4];
                    a[mt][3] = As[ba + 8 * LDW + 4];
                }
#pragma unroll
                for (int nb = 0; nb < 8; nb++) {
                    int bb = b_base + nb * 8 * LDW + ko;
                    b[nb][0] = Bs[bb];
                    b[nb][1] = Bs[bb + 4];
                }
#pragma unroll
                for (int mt = 0; mt < 2; mt++)
#pragma unroll
                    for (int nb = 0; nb < 8; nb++) mma16h(accN[mt][nb], a[mt], b[nb]);
            }
            if (do_main) {
                const int kc8 = (ks >> 1) * 8;       // k-chunk word offset
                if ((ks & 1) == 0) {                 // load A-dup for this chunk
#pragma unroll
                    for (int r = 0; r < 4; r++) {
                        int row = wm * 32 + (r >> 1) * 16 + (r & 1) * 8 + g;
                        const uint32_t* ap = &smw[ADUP_OFF + row * 36 + kc8];
                        uint4 v0 = *(const uint4*)ap;
                        uint4 v1 = *(const uint4*)(ap + 4);
                        adup[r][0] = v0.x; adup[r][1] = v0.y; adup[r][2] = v0.z; adup[r][3] = v0.w;
                        adup[r][4] = v1.x; adup[r][5] = v1.y; adup[r][6] = v1.z; adup[r][7] = v1.w;
                    }
                }
                const int nbs = (ks & 1) * 4;
#pragma unroll
                for (int nb = nbs; nb < nbs + 4; nb++) {
                    int p = wn * 32 + nb * 4 + t;
                    const uint32_t* bpp = &smw[bp_off + p * 36 + kc8];
                    uint4 b0 = *(const uint4*)bpp;
                    uint4 b1 = *(const uint4*)(bpp + 4);
                    uint32_t bw[8] = {b0.x, b0.y, b0.z, b0.w, b1.x, b1.y, b1.z, b1.w};
#pragma unroll
                    for (int r = 0; r < 4; r++) {
#pragma unroll
                        for (int j = 0; j < 8; j++)
                            hfma2(accN[r >> 1][nb][r & 1], adup[r][j], bw[j]);
                    }
                }
            }
            if (do_epi) {
                float2 nc = *(const float2*)&nsm[(tt - 1) * 128 + wn * 64 + ks * 8 + t * 2];
#pragma unroll
                for (int mt = 0; mt < 2; mt++) {
#pragma unroll
                    for (int h = 0; h < 2; h++) {
                        float2 dot = __half22float2(*(__half2*)&accO[mt][ks][h]);
                        float base = nr[mt][h];
                        float sq0 = fmaxf(fmaf(-2.f, dot.x, base + nc.x), 0.f);
                        float sq1 = fmaxf(fmaf(-2.f, dot.y, base + nc.y), 0.f);
                        float d0, d1, e0, e1;
                        asm("sqrt.approx.f32 %0, %1;" : "=f"(d0) : "f"(sq0));
                        asm("sqrt.approx.f32 %0, %1;" : "=f"(d1) : "f"(sq1));
                        asm("ex2.approx.f32 %0, %1;" : "=f"(e0) : "f"(d0 * -1.4426950408889634f));
                        asm("ex2.approx.f32 %0, %1;" : "=f"(e1) : "f"(d1 * -1.4426950408889634f));
                        rs[mt][h] += e0 + e1;
                    }
                }
            }
        }

        if (do_epi) {
#pragma unroll
            for (int mt = 0; mt < 2; mt++) {
#pragma unroll
                for (int h = 0; h < 2; h++) {
                    float v = rs[mt][h];
                    v += __shfl_xor_sync(0xffffffffu, v, 1);
                    v += __shfl_xor_sync(0xffffffffu, v, 2);
                    if (t == 0) {
                        int r_local = wm * 32 + mt * 16 + h * 8 + g;
                        g_partial[((size_t)(bm * TILE + r_local) * nt + bn_old) * 2 + wn] = v;
                    }
                }
            }
        }

        if (do_main) {
            CP_WAIT0();
            __syncthreads();
        }
    }
}

// ---------------------------------------------------------------------------
__global__ void rows_kernel(int B, int nt) {
    __shared__ float sm[256];
    int i = blockIdx.x * blockDim.x + threadIdx.x;
    float rv = 0.f;
    if (i < B) {
        float s = 0.f;
        const float* p = g_partial + (size_t)i * nt * 2;
        for (int t = 0; t < 2 * nt; t++) s += p[t];
        rv = logf(s) + g_diag[i];
    }
    sm[threadIdx.x] = rv;
    __syncthreads();
    for (int o = 128; o; o >>= 1) {
        if (threadIdx.x < o) sm[threadIdx.x] += sm[threadIdx.x + o];
        __syncthreads();
    }
    if (threadIdx.x == 0) g_bsum[blockIdx.x] = sm[0];
}

__global__ void final_kernel(float* __restrict__ out, int B, int nblk, int out_size) {
    if (threadIdx.x == 0) {
        float s = 0.f;
        for (int i = 0; i < nblk; i++) s += g_bsum[i];
        float loss = s / (float)B;
        for (int i = 0; i < out_size; i++) out[i] = loss;
    }
}

extern "C" void kernel_launch(void* const* d_in, const int* in_sizes, int n_in,
                              void* d_out, int out_size) {
    const float* sk = (const float*)d_in[0];
    const float* im = (const float*)d_in[1];
    float* out = (float*)d_out;

    int B = in_sizes[0] / DIM;   // 8192
    int nt = B / TILE;           // 64

    prep_kernel<<<dim3(B / 8, 4), 256>>>(sk, im, B);

    static const int SMEM_BYTES = SMEM_WORDS * 4;   // 118784
    cudaFuncSetAttribute(dist_mma, cudaFuncAttributeMaxDynamicSharedMemorySize, SMEM_BYTES);
    int ncta = nt * (nt / TPB);  // 1024
    dist_mma<<<ncta, 256, SMEM_BYTES>>>(nt);

    int nblk = (B + 255) / 256;  // 32
    rows_kernel<<<nblk, 256>>>(B, nt);
    final_kernel<<<1, 32>>>(out, B, nblk, out_size);
}

// round 13
// speedup vs baseline: 1.1194x; 1.1194x over previous
#include <cuda_runtime.h>
#include <cuda_fp16.h>
#include <cstdint>
#include <math.h>

#define DIM 128
#define TILE 128
#define BMAX 8192
#define NTMAX 64
#define LDW 68                 // smem row stride in words (272B): banks (4g+t)%32 distinct

// smem word offsets: A double buf, B double buf, norms double buf
#define AB_W   (128 * LDW)             // 8704 per buffer
#define B_OFF  (2 * AB_W)              // 17408
#define N_OFF  (4 * AB_W)              // 34816
#define SMEM_WORDS (N_OFF + 1024)      // 35840 -> 143360 bytes

__device__ float g_nsk[BMAX];
__device__ float g_nim[BMAX];
__device__ uint32_t g_skh[BMAX * 64];                     // f16x2-packed rows
__device__ uint32_t g_imh[BMAX * 64];
__device__ float g_partial[(size_t)BMAX * NTMAX * 2];     // per (row, bn, wn-half)
__device__ float g_diag[BMAX];                            // exact fp32 diagonal distance
__device__ float g_bsum[32];
__device__ unsigned g_cnt;

static __device__ __forceinline__ uint32_t s2u(const void* p) {
    uint32_t a;
    asm("{ .reg .u64 t; cvta.to.shared.u64 t, %1; cvt.u32.u64 %0, t; }" : "=r"(a) : "l"(p));
    return a;
}
static __device__ __forceinline__ void cpa16(uint32_t dst, const void* src) {
    asm volatile("cp.async.cg.shared.global [%0], [%1], 16;" :: "r"(dst), "l"(src) : "memory");
}
#define CP_COMMIT() asm volatile("cp.async.commit_group;" ::: "memory")
#define CP_WAIT0()  asm volatile("cp.async.wait_group 0;" ::: "memory")

static __device__ __forceinline__ void mma16h(uint32_t* c, const uint32_t* a, const uint32_t* b) {
    asm("mma.sync.aligned.m16n8k16.row.col.f16.f16.f16.f16 "
        "{%0,%1}, {%2,%3,%4,%5}, {%6,%7}, {%0,%1};"
        : "+r"(c[0]), "+r"(c[1])
        : "r"(a[0]), "r"(a[1]), "r"(a[2]), "r"(a[3]), "r"(b[0]), "r"(b[1]));
}

// ---------------------------------------------------------------------------
// One warp per row: y=0/1 -> fp32 norms + f16 pack; y=2 -> exact fp32 diag.
// Also resets the rows/final completion counter.
// ---------------------------------------------------------------------------
__global__ void prep_kernel(const float* __restrict__ sk,
                            const float* __restrict__ im, int B) {
    if (blockIdx.x == 0 && blockIdx.y == 0 && threadIdx.x == 0) g_cnt = 0u;
    int row = (blockIdx.x * blockDim.x + threadIdx.x) >> 5;
    int lane = threadIdx.x & 31;
    if (row >= B) return;
    if (blockIdx.y < 2) {
        const float* src = blockIdx.y ? im : sk;
        float* ndst = blockIdx.y ? g_nim : g_nsk;
        uint32_t* bdst = blockIdx.y ? g_imh : g_skh;
        float4 v = ((const float4*)(src + (size_t)row * DIM))[lane];
        __half2 h0 = __floats2half2_rn(v.x, v.y);
        __half2 h1 = __floats2half2_rn(v.z, v.w);
        bdst[row * 64 + lane * 2]     = *(uint32_t*)&h0;
        bdst[row * 64 + lane * 2 + 1] = *(uint32_t*)&h1;
        float s = v.x * v.x + v.y * v.y + v.z * v.z + v.w * v.w;
#pragma unroll
        for (int o = 16; o; o >>= 1) s += __shfl_xor_sync(0xffffffffu, s, o);
        if (lane == 0) ndst[row] = s;
    } else {
        float4 a = ((const float4*)(sk + (size_t)row * DIM))[lane];
        float4 b = ((const float4*)(im + (size_t)row * DIM))[lane];
        float dx = a.x - b.x, dy = a.y - b.y, dz = a.z - b.z, dw = a.w - b.w;
        float s = dx * dx + dy * dy + dz * dz + dw * dw;
#pragma unroll
        for (int o = 16; o; o >>= 1) s += __shfl_xor_sync(0xffffffffu, s, o);
        if (lane == 0) g_diag[row] = sqrtf(s);
    }
}

// ---------------------------------------------------------------------------
// Persistent flat-pipelined f16-acc MMA + fused distance/exp epilogue.
// grid = #SMs. Each CTA owns groups {bid, bid+G, ...}; group = (bm, 4 bn-tiles).
// All tiles form ONE software-pipelined stream: B prefetched every tile,
// A+norms prefetched 2 tiles before each group switch. One prologue wait and
// one tail epilogue per CTA total.
// ---------------------------------------------------------------------------
__global__ void __launch_bounds__(256, 1)
dist_mma(int nt, int NG) {
    extern __shared__ uint32_t smw[];
    const uint32_t sbase = s2u(smw);
    float* nsm = (float*)(smw + N_OFF);

    const int tid = threadIdx.x;
    const int wid = tid >> 5;
    const int lane = tid & 31;
    const int gl = lane >> 2;
    const int t = lane & 3;
    const int wm = wid & 3;        // m-block: 32 rows
    const int wn = wid >> 2;       // n-block: 64 cols

    const int bid = blockIdx.x;
    const int G = gridDim.x;
    const int ntg = nt >> 2;                        // groups per bm (16)
    const int ngrp = (NG - 1 - bid) / G + 1;        // my group count
    const int T = ngrp * 4;                         // my tile count

    // ---- prologue: group 0's A + norms + tile 0's B ----
    {
        const int grp0 = bid;
        const int bm0 = grp0 / ntg;
        const int w0 = grp0 % ntg;
        const uint32_t* Ag = g_skh + (size_t)bm0 * TILE * 64;
        const uint32_t* Bg = g_imh + (size_t)(w0 * 4) * TILE * 64;
#pragma unroll
        for (int it = 0; it < 8; it++) {
            int c = it * 256 + tid;
            int row = c >> 4, ch = c & 15;
            uint32_t doff = (uint32_t)row * 272 + (uint32_t)ch * 16;
            cpa16(sbase + doff, Ag + row * 64 + ch * 4);
            cpa16(sbase + B_OFF * 4 + doff, Bg + row * 64 + ch * 4);
        }
        if (tid < 128)
            cpa16(sbase + N_OFF * 4 + (uint32_t)tid * 16, g_nim + (size_t)(w0 * 4) * TILE + tid * 4);
        CP_COMMIT();
        CP_WAIT0();
    }
    __syncthreads();

    float nr_cur[2][2], nr_epi[2][2];
    {
        const int bm0 = bid / ntg;
#pragma unroll
        for (int mt = 0; mt < 2; mt++)
#pragma unroll
            for (int h = 0; h < 2; h++)
                nr_cur[mt][h] = g_nsk[bm0 * TILE + wm * 32 + mt * 16 + h * 8 + gl];
    }

    const int a_thr = (wm * 32 + gl) * LDW + t;
    const int b_thr = (wn * 64 + gl) * LDW + t;

    uint32_t acc[2][2][8][2];      // [buf][mt][nb][h]  packed f16x2
    float rs[2][2];
    int bm_prev = 0, bn_prev = 0;

    for (int tt = 0; tt <= T; tt++) {
        const bool do_main = (tt < T);
        const bool do_epi = (tt > 0);
        const int grp_idx = tt >> 2;
        const int slot = tt & 3;

        // norms-for-epilogue tracking (bm changes only at slot 0)
#pragma unroll
        for (int mt = 0; mt < 2; mt++)
#pragma unroll
            for (int h = 0; h < 2; h++) nr_epi[mt][h] = nr_cur[mt][h];

        int bm = 0, bn = 0;
        if (do_main) {
            const int grp = bid + grp_idx * G;
            bm = grp / ntg;
            bn = (grp % ntg) * 4 + slot;
            if (slot == 0 && tt > 0) {
#pragma unroll
                for (int mt = 0; mt < 2; mt++)
#pragma unroll
                    for (int h = 0; h < 2; h++)
                        nr_cur[mt][h] = g_nsk[bm * TILE + wm * 32 + mt * 16 + h * 8 + gl];
            }

            // ---- prefetch: B for tile tt+1; A+norms for next group at slot 2 ----
            const int u = tt + 1;
            if (u < T) {
                const int grpu = bid + (u >> 2) * G;
                const int bnu = (grpu % ntg) * 4 + (u & 3);
                const uint32_t* Bg = g_imh + (size_t)bnu * TILE * 64;
                uint32_t dbuf = sbase + (B_OFF + (u & 1) * AB_W) * 4;
#pragma unroll
                for (int it = 0; it < 8; it++) {
                    int c = it * 256 + tid;
                    int row = c >> 4, ch = c & 15;
                    cpa16(dbuf + (uint32_t)row * 272 + (uint32_t)ch * 16, Bg + row * 64 + ch * 4);
                }
            }
            if (slot == 2 && grp_idx + 1 < ngrp) {
                const int gg = bid + (grp_idx + 1) * G;
                const int bmn = gg / ntg;
                const int wn2 = gg % ntg;
                const uint32_t* Ag = g_skh + (size_t)bmn * TILE * 64;
                uint32_t abuf = sbase + ((uint32_t)((grp_idx + 1) & 1) * AB_W) * 4;
#pragma unroll
                for (int it = 0; it < 8; it++) {
                    int c = it * 256 + tid;
                    int row = c >> 4, ch = c & 15;
                    cpa16(abuf + (uint32_t)row * 272 + (uint32_t)ch * 16, Ag + row * 64 + ch * 4);
                }
                if (tid < 128)
                    cpa16(sbase + (N_OFF + ((grp_idx + 1) & 1) * 512) * 4 + (uint32_t)tid * 16,
                          g_nim + (size_t)(wn2 * 4) * TILE + tid * 4);
            }
            CP_COMMIT();
        }

        uint32_t (*accN)[8][2] = acc[tt & 1];
        uint32_t (*accO)[8][2] = acc[(tt & 1) ^ 1];
        const uint32_t* As = smw + (grp_idx & 1) * AB_W;
        const uint32_t* Bs = smw + B_OFF + (tt & 1) * AB_W;
        // epilogue norm block for tile tt-1
        const int pgrp = (tt - 1) >> 2;
        const float* nce = &nsm[(pgrp & 1) * 512 + ((tt - 1) & 3) * 128 + wn * 64 + t * 2];

        if (do_main) {
#pragma unroll
            for (int mt = 0; mt < 2; mt++)
#pragma unroll
                for (int nb = 0; nb < 8; nb++) {
                    accN[mt][nb][0] = 0u;
                    accN[mt][nb][1] = 0u;
                }
        }
        if (do_epi) { rs[0][0] = rs[0][1] = rs[1][0] = rs[1][1] = 0.f; }

        // 8 k-steps of 16; 1 epilogue chunk (nb=ks) of the previous tile per step
#pragma unroll
        for (int ks = 0; ks < 8; ks++) {
            if (do_main) {
                const int ko = ks * 8;
                uint32_t a[2][4], b[8][2];
#pragma unroll
                for (int mt = 0; mt < 2; mt++) {
                    int ba = a_thr + mt * 16 * LDW + ko;
                    a[mt][0] = As[ba];
                    a[mt][1] = As[ba + 8 * LDW];
                    a[mt][2] = As[ba + 4];
                    a[mt][3] = As[ba + 8 * LDW + 4];
                }
#pragma unroll
                for (int nb = 0; nb < 8; nb++) {
                    int bb = b_thr + nb * 8 * LDW + ko;
                    b[nb][0] = Bs[bb];
                    b[nb][1] = Bs[bb + 4];
                }
#pragma unroll
                for (int mt = 0; mt < 2; mt++)
#pragma unroll
                    for (int nb = 0; nb < 8; nb++) mma16h(accN[mt][nb], a[mt], b[nb]);
            }
            if (do_epi) {
                float2 nc = *(const float2*)(nce + ks * 8);
#pragma unroll
                for (int mt = 0; mt < 2; mt++) {
#pragma unroll
                    for (int h = 0; h < 2; h++) {
                        float2 dot = __half22float2(*(__half2*)&accO[mt][ks][h]);
                        float base = nr_epi[mt][h];
                        float sq0 = fmaxf(fmaf(-2.f, dot.x, base + nc.x), 0.f);
                        float sq1 = fmaxf(fmaf(-2.f, dot.y, base + nc.y), 0.f);
                        float d0, d1, e0, e1;
                        asm("sqrt.approx.f32 %0, %1;" : "=f"(d0) : "f"(sq0));
                        asm("sqrt.approx.f32 %0, %1;" : "=f"(d1) : "f"(sq1));
                        asm("ex2.approx.f32 %0, %1;" : "=f"(e0) : "f"(d0 * -1.4426950408889634f));
                        asm("ex2.approx.f32 %0, %1;" : "=f"(e1) : "f"(d1 * -1.4426950408889634f));
                        rs[mt][h] += e0 + e1;
                    }
                }
            }
        }

        if (do_epi) {
#pragma unroll
            for (int mt = 0; mt < 2; mt++) {
#pragma unroll
                for (int h = 0; h < 2; h++) {
                    float v = rs[mt][h];
                    v += __shfl_xor_sync(0xffffffffu, v, 1);
                    v += __shfl_xor_sync(0xffffffffu, v, 2);
                    if (t == 0) {
                        int r_local = wm * 32 + mt * 16 + h * 8 + gl;
                        g_partial[((size_t)(bm_prev * TILE + r_local) * nt + bn_prev) * 2 + wn] = v;
                    }
                }
            }
        }

        if (do_main) {
            bm_prev = bm;
            bn_prev = bn;
            CP_WAIT0();
            __syncthreads();
        }
    }
}

// ---------------------------------------------------------------------------
// Per-row lse + exact diag, block partial sums; last block finishes the mean.
// All reduction orders fixed -> deterministic.
// ---------------------------------------------------------------------------
__global__ void rows_kernel(float* __restrict__ out, int B, int nt, int out_size) {
    __shared__ float sm[256];
    int i = blockIdx.x * blockDim.x + threadIdx.x;
    float rv = 0.f;
    if (i < B) {
        float s = 0.f;
        const float* p = g_partial + (size_t)i * nt * 2;
        for (int t = 0; t < 2 * nt; t++) s += p[t];
        rv = logf(s) + g_diag[i];
    }
    sm[threadIdx.x] = rv;
    __syncthreads();
    for (int o = 128; o; o >>= 1) {
        if (threadIdx.x < o) sm[threadIdx.x] += sm[threadIdx.x + o];
        __syncthreads();
    }
    if (threadIdx.x == 0) {
        g_bsum[blockIdx.x] = sm[0];
        __threadfence();
        unsigned done = atomicAdd(&g_cnt, 1u);
        if (done == gridDim.x - 1) {
            float s = 0.f;
            for (unsigned b = 0; b < gridDim.x; b++) s += g_bsum[b];
            float loss = s / (float)B;
            for (int k = 0; k < out_size; k++) out[k] = loss;
            g_cnt = 0u;
        }
    }
}

extern "C" void kernel_launch(void* const* d_in, const int* in_sizes, int n_in,
                              void* d_out, int out_size) {
    const float* sk = (const float*)d_in[0];
    const float* im = (const float*)d_in[1];
    float* out = (float*)d_out;

    int B = in_sizes[0] / DIM;   // 8192
    int nt = B / TILE;           // 64
    int NG = nt * (nt / 4);      // 1024 groups

    prep_kernel<<<dim3(B / 8, 3), 256>>>(sk, im, B);

    int dev = 0, nsm = 148;
    cudaGetDevice(&dev);
    cudaDeviceGetAttribute(&nsm, cudaDevAttrMultiProcessorCount, dev);
    if (nsm < 1) nsm = 148;
    if (nsm > NG) nsm = NG;

    static const int SMEM_BYTES = SMEM_WORDS * 4;   // 143360
    cudaFuncSetAttribute(dist_mma, cudaFuncAttributeMaxDynamicSharedMemorySize, SMEM_BYTES);
    dist_mma<<<nsm, 256, SMEM_BYTES>>>(nt, NG);

    rows_kernel<<<(B + 255) / 256, 256>>>(out, B, nt, out_size);
}

// round 14
// speedup vs baseline: 1.8329x; 1.6374x over previous
#include <cuda_runtime.h>
#include <cuda_fp16.h>
#include <cstdint>
#include <math.h>

#define DIM 128
#define TILE 128
#define BMAX 8192
#define LDW 68                 // smem row stride in words (272B): banks (4g+t)%32 distinct

#define AB_W   (128 * LDW)             // 8704 words per A/B buffer
#define B_OFF  (2 * AB_W)              // 17408
#define N_OFF  (4 * AB_W)              // 34816
#define SMEM_WORDS (N_OFF + 1024)      // 35840 -> 143360 bytes

__device__ float g_nsk[BMAX];
__device__ float g_nim[BMAX];
__device__ uint32_t g_skh[BMAX * 64];                     // f16x2-packed rows
__device__ uint32_t g_imh[BMAX * 64];
__device__ float g_partial[(size_t)BMAX * 64 * 2];        // per (row, bn, wn-half)
__device__ float g_diag[BMAX];                            // exact fp32 diagonal distance
__device__ float g_bsum[32];
__device__ unsigned g_cnt;

static __device__ __forceinline__ uint32_t s2u(const void* p) {
    uint32_t a;
    asm("{ .reg .u64 t; cvta.to.shared.u64 t, %1; cvt.u32.u64 %0, t; }" : "=r"(a) : "l"(p));
    return a;
}
static __device__ __forceinline__ void cpa16(uint32_t dst, const void* src) {
    asm volatile("cp.async.cg.shared.global [%0], [%1], 16;" :: "r"(dst), "l"(src) : "memory");
}
#define CP_COMMIT() asm volatile("cp.async.commit_group;" ::: "memory")
#define CP_WAIT0()  asm volatile("cp.async.wait_group 0;" ::: "memory")

static __device__ __forceinline__ void mma16h(uint32_t* c, const uint32_t* a, const uint32_t* b) {
    asm("mma.sync.aligned.m16n8k16.row.col.f16.f16.f16.f16 "
        "{%0,%1}, {%2,%3,%4,%5}, {%6,%7}, {%0,%1};"
        : "+r"(c[0]), "+r"(c[1])
        : "r"(a[0]), "r"(a[1]), "r"(a[2]), "r"(a[3]), "r"(b[0]), "r"(b[1]));
}

// ---------------------------------------------------------------------------
// prep: y=0/1 -> fp32 norms + f16 pack; y=2 -> exact fp32 diag. Resets g_cnt.
// ---------------------------------------------------------------------------
__global__ void prep_kernel(const float* __restrict__ sk,
                            const float* __restrict__ im, int B) {
    if (blockIdx.x == 0 && blockIdx.y == 0 && threadIdx.x == 0) g_cnt = 0u;
    int row = (blockIdx.x * blockDim.x + threadIdx.x) >> 5;
    int lane = threadIdx.x & 31;
    if (row >= B) return;
    if (blockIdx.y < 2) {
        const float* src = blockIdx.y ? im : sk;
        float* ndst = blockIdx.y ? g_nim : g_nsk;
        uint32_t* bdst = blockIdx.y ? g_imh : g_skh;
        float4 v = ((const float4*)(src + (size_t)row * DIM))[lane];
        __half2 h0 = __floats2half2_rn(v.x, v.y);
        __half2 h1 = __floats2half2_rn(v.z, v.w);
        bdst[row * 64 + lane * 2]     = *(uint32_t*)&h0;
        bdst[row * 64 + lane * 2 + 1] = *(uint32_t*)&h1;
        float s = v.x * v.x + v.y * v.y + v.z * v.z + v.w * v.w;
#pragma unroll
        for (int o = 16; o; o >>= 1) s += __shfl_xor_sync(0xffffffffu, s, o);
        if (lane == 0) ndst[row] = s;
    } else {
        float4 a = ((const float4*)(sk + (size_t)row * DIM))[lane];
        float4 b = ((const float4*)(im + (size_t)row * DIM))[lane];
        float dx = a.x - b.x, dy = a.y - b.y, dz = a.z - b.z, dw = a.w - b.w;
        float s = dx * dx + dy * dy + dz * dz + dw * dw;
#pragma unroll
        for (int o = 16; o; o >>= 1) s += __shfl_xor_sync(0xffffffffu, s, o);
        if (lane == 0) g_diag[row] = sqrtf(s);
    }
}

// ---- macros: all buffer/acc indices are compile-time literals ----

#define LOAD_B_TILE(bnv, bufp) do {                                            \
    const uint32_t* Bg_ = g_imh + (size_t)(bnv) * 128 * 64;                    \
    uint32_t dbuf_ = sbase + (uint32_t)(B_OFF + (bufp) * AB_W) * 4;            \
    _Pragma("unroll")                                                          \
    for (int it_ = 0; it_ < 8; it_++) {                                        \
        int c_ = it_ * 256 + tid;                                              \
        int row_ = c_ >> 4, ch_ = c_ & 15;                                     \
        cpa16(dbuf_ + (uint32_t)row_ * 272 + (uint32_t)ch_ * 16,               \
              Bg_ + row_ * 64 + ch_ * 4);                                      \
    }                                                                          \
} while (0)

#define LOAD_A_NORMS(grpv, bufp) do {                                          \
    int bmL_ = (grpv) / ntg, wL_ = (grpv) % ntg;                               \
    const uint32_t* Ag_ = g_skh + (size_t)bmL_ * 128 * 64;                     \
    uint32_t abuf_ = sbase + (uint32_t)((bufp) * AB_W) * 4;                    \
    _Pragma("unroll")                                                          \
    for (int it_ = 0; it_ < 8; it_++) {                                        \
        int c_ = it_ * 256 + tid;                                              \
        int row_ = c_ >> 4, ch_ = c_ & 15;                                     \
        cpa16(abuf_ + (uint32_t)row_ * 272 + (uint32_t)ch_ * 16,               \
              Ag_ + row_ * 64 + ch_ * 4);                                      \
    }                                                                          \
    if (tid < 128)                                                             \
        cpa16(sbase + (uint32_t)(N_OFF + (bufp) * 512) * 4 + (uint32_t)tid * 16, \
              g_nim + (size_t)(wL_ * 4) * 128 + tid * 4);                      \
} while (0)

#define LOAD_NR(dst, bmv) do {                                                 \
    _Pragma("unroll")                                                          \
    for (int mt_ = 0; mt_ < 2; mt_++)                                          \
        _Pragma("unroll")                                                      \
        for (int h_ = 0; h_ < 2; h_++)                                         \
            dst[mt_][h_] = g_nsk[(bmv) * 128 + wm * 32 + mt_ * 16 + h_ * 8 + gl]; \
} while (0)

#define EPI_PAIR(CUR, KS, NCX, NCY, NRE) do {                                  \
    _Pragma("unroll")                                                          \
    for (int mt_ = 0; mt_ < 2; mt_++) {                                        \
        _Pragma("unroll")                                                      \
        for (int h_ = 0; h_ < 2; h_++) {                                       \
            float2 dot_ = __half22float2(*(__half2*)&acc[1 - (CUR)][mt_][KS][h_]); \
            float base_ = NRE[mt_][h_];                                        \
            float sq0_ = fmaxf(fmaf(-2.f, dot_.x, base_ + (NCX)), 0.f);        \
            float sq1_ = fmaxf(fmaf(-2.f, dot_.y, base_ + (NCY)), 0.f);        \
            float d0_, d1_, e0_, e1_;                                          \
            asm("sqrt.approx.f32 %0, %1;" : "=f"(d0_) : "f"(sq0_));            \
            asm("sqrt.approx.f32 %0, %1;" : "=f"(d1_) : "f"(sq1_));            \
            asm("ex2.approx.f32 %0, %1;" : "=f"(e0_) : "f"(d0_ * -1.4426950408889634f)); \
            asm("ex2.approx.f32 %0, %1;" : "=f"(e1_) : "f"(d1_ * -1.4426950408889634f)); \
            rs_[mt_][h_] += e0_ + e1_;                                         \
        }                                                                      \
    }                                                                          \
} while (0)

#define EPI_REDUCE_STORE() do {                                                \
    _Pragma("unroll")                                                          \
    for (int mt_ = 0; mt_ < 2; mt_++) {                                        \
        _Pragma("unroll")                                                      \
        for (int h_ = 0; h_ < 2; h_++) {                                       \
            float v_ = rs_[mt_][h_];                                           \
            v_ += __shfl_xor_sync(0xffffffffu, v_, 1);                         \
            v_ += __shfl_xor_sync(0xffffffffu, v_, 2);                         \
            if (t == 0) {                                                      \
                int rl_ = wm * 32 + mt_ * 16 + h_ * 8 + gl;                    \
                g_partial[((size_t)(bm_prev * 128 + rl_) * nt + bn_prev) * 2 + wn] = v_; \
            }                                                                  \
        }                                                                      \
    }                                                                          \
} while (0)

// One tile: zero acc[CUR], 8 k-steps MMA from A-buf AB / B-buf CUR, with the
// previous tile's epilogue (acc[1-CUR], norm buf NBE slot PSLOT, norms NRE)
// interleaved per k-step under runtime-uniform guard EPIC.
#define TILE_BODY(CUR, AB, NBE, PSLOT, NRE, EPIC) do {                         \
    const uint32_t* As_ = smw + (AB) * AB_W;                                   \
    const uint32_t* Bs_ = smw + B_OFF + (CUR) * AB_W;                          \
    const float* nce_ = nsm + (NBE) * 512 + (PSLOT) * 128 + wn * 64 + t * 2;   \
    const bool epi_ = (EPIC);                                                  \
    _Pragma("unroll")                                                          \
    for (int mt_ = 0; mt_ < 2; mt_++)                                          \
        _Pragma("unroll")                                                      \
        for (int nb_ = 0; nb_ < 8; nb_++) {                                    \
            acc[CUR][mt_][nb_][0] = 0u;                                        \
            acc[CUR][mt_][nb_][1] = 0u;                                        \
        }                                                                      \
    float rs_[2][2] = {{0.f, 0.f}, {0.f, 0.f}};                                \
    _Pragma("unroll")                                                          \
    for (int ks_ = 0; ks_ < 8; ks_++) {                                        \
        const int ko_ = ks_ * 8;                                               \
        uint32_t a_[2][4], b_[8][2];                                           \
        _Pragma("unroll")                                                      \
        for (int mt_ = 0; mt_ < 2; mt_++) {                                    \
            int ba_ = a_thr + mt_ * 16 * LDW + ko_;                            \
            a_[mt_][0] = As_[ba_];                                             \
            a_[mt_][1] = As_[ba_ + 8 * LDW];                                   \
            a_[mt_][2] = As_[ba_ + 4];                                         \
            a_[mt_][3] = As_[ba_ + 8 * LDW + 4];                               \
        }                                                                      \
        _Pragma("unroll")                                                      \
        for (int nb_ = 0; nb_ < 8; nb_++) {                                    \
            int bb_ = b_thr + nb_ * 8 * LDW + ko_;                             \
            b_[nb_][0] = Bs_[bb_];                                             \
            b_[nb_][1] = Bs_[bb_ + 4];                                         \
        }                                                                      \
        _Pragma("unroll")                                                      \
        for (int mt_ = 0; mt_ < 2; mt_++)                                      \
            _Pragma("unroll")                                                  \
            for (int nb_ = 0; nb_ < 8; nb_++)                                  \
                mma16h(acc[CUR][mt_][nb_], a_[mt_], b_[nb_]);                  \
        if (epi_) {                                                            \
            float2 nc_ = *(const float2*)(nce_ + ks_ * 8);                     \
            EPI_PAIR(CUR, ks_, nc_.x, nc_.y, NRE);                             \
        }                                                                      \
    }                                                                          \
    if (epi_) EPI_REDUCE_STORE();                                              \
} while (0)

// ---------------------------------------------------------------------------
// Persistent flat-pipelined f16-acc MMA + fused distance/exp epilogue.
// grid = #SMs; groups (bm, 4 bn-tiles) processed in PAIRS with a fully
// unrolled 8-tile body so every acc/buffer index is compile-time (no spills).
// ---------------------------------------------------------------------------
__global__ void __launch_bounds__(256, 1)
dist_mma(int nt, int NG) {
    extern __shared__ uint32_t smw[];
    const uint32_t sbase = s2u(smw);
    float* nsm = (float*)(smw + N_OFF);

    const int tid = threadIdx.x;
    const int wid = tid >> 5;
    const int lane = tid & 31;
    const int gl = lane >> 2;
    const int t = lane & 3;
    const int wm = wid & 3;        // m-block: 32 rows
    const int wn = wid >> 2;       // n-block: 64 cols

    const int bid = blockIdx.x;
    const int G = gridDim.x;
    const int ntg = nt >> 2;                        // groups per bm (16)
    const int ngrp = (NG - 1 - bid) / G + 1;
    const int npairs = ngrp >> 1;
    const bool tailg = (ngrp & 1) != 0;

    // ---- prologue: group 0's A + norms (buf 0) + tile 0's B (buf 0) ----
    LOAD_A_NORMS(bid, 0);
    LOAD_B_TILE((bid % ntg) * 4, 0);
    CP_COMMIT();
    CP_WAIT0();
    __syncthreads();

    float nr_cur[2][2], nr_epi[2][2];
    LOAD_NR(nr_cur, bid / ntg);
#pragma unroll
    for (int mt = 0; mt < 2; mt++)
#pragma unroll
        for (int h = 0; h < 2; h++) nr_epi[mt][h] = nr_cur[mt][h];

    const int a_thr = (wm * 32 + gl) * LDW + t;
    const int b_thr = (wn * 64 + gl) * LDW + t;

    uint32_t acc[2][2][8][2];      // [buf][mt][nb][h]  packed f16x2, literal-indexed only
    int bm_prev = 0, bn_prev = 0;

    // STEP: S, SGRP=(S>>2), AB=SGRP, CUR=S&1, NBE, PSLOT=(S+3)&3 all literals.
#define STEP_PAIR(S, NBE_, NRE_, EPIC_) do {                                   \
        const int grp_ = bid + (2 * gp + ((S) >> 2)) * G;                      \
        const int bm_ = grp_ / ntg;                                            \
        const int bn_ = (grp_ % ntg) * 4 + ((S) & 3);                          \
        if (((S) & 3) == 0) {                                                  \
            _Pragma("unroll")                                                  \
            for (int mt_ = 0; mt_ < 2; mt_++)                                  \
                _Pragma("unroll")                                              \
                for (int h_ = 0; h_ < 2; h_++) nr_epi[mt_][h_] = nr_cur[mt_][h_]; \
            LOAD_NR(nr_cur, bm_);                                              \
        }                                                                      \
        if ((S) < 7) {                                                         \
            const int grpn_ = bid + (2 * gp + (((S) + 1) >> 2)) * G;           \
            LOAD_B_TILE((grpn_ % ntg) * 4 + (((S) + 1) & 3), ((S) + 1) & 1);   \
        } else if (2 * gp + 2 < ngrp) {                                        \
            const int grpn_ = bid + (2 * gp + 2) * G;                          \
            LOAD_B_TILE((grpn_ % ntg) * 4, 0);                                 \
        }                                                                      \
        if ((S) == 2) LOAD_A_NORMS(bid + (2 * gp + 1) * G, 1);                 \
        if ((S) == 6 && 2 * gp + 2 < ngrp) LOAD_A_NORMS(bid + (2 * gp + 2) * G, 0); \
        CP_COMMIT();                                                           \
        TILE_BODY((S) & 1, (S) >> 2, NBE_, ((S) + 3) & 3, NRE_, EPIC_);        \
        bm_prev = bm_; bn_prev = bn_;                                          \
        CP_WAIT0();                                                            \
        __syncthreads();                                                       \
    } while (0)

    for (int gp = 0; gp < npairs; gp++) {
        STEP_PAIR(0, 1, nr_epi, (gp != 0));
        STEP_PAIR(1, 0, nr_cur, true);
        STEP_PAIR(2, 0, nr_cur, true);
        STEP_PAIR(3, 0, nr_cur, true);
        STEP_PAIR(4, 0, nr_epi, true);
        STEP_PAIR(5, 1, nr_cur, true);
        STEP_PAIR(6, 1, nr_cur, true);
        STEP_PAIR(7, 1, nr_cur, true);
    }

    if (tailg) {
        const int grpT = bid + 2 * npairs * G;
        const int bmT = grpT / ntg;
        const int bnT0 = (grpT % ntg) * 4;
#define STEP_TAIL(S, NBE_, NRE_, EPIC_) do {                                   \
        if (((S) & 3) == 0) {                                                  \
            _Pragma("unroll")                                                  \
            for (int mt_ = 0; mt_ < 2; mt_++)                                  \
                _Pragma("unroll")                                              \
                for (int h_ = 0; h_ < 2; h_++) nr_epi[mt_][h_] = nr_cur[mt_][h_]; \
            LOAD_NR(nr_cur, bmT);                                              \
        }                                                                      \
        if ((S) < 3) LOAD_B_TILE(bnT0 + (S) + 1, ((S) + 1) & 1);               \
        CP_COMMIT();                                                           \
        TILE_BODY((S) & 1, 0, NBE_, ((S) + 3) & 3, NRE_, EPIC_);               \
        bm_prev = bmT; bn_prev = bnT0 + (S);                                   \
        CP_WAIT0();                                                            \
        __syncthreads();                                                       \
    } while (0)
        STEP_TAIL(0, 1, nr_epi, (npairs != 0));
        STEP_TAIL(1, 0, nr_cur, true);
        STEP_TAIL(2, 0, nr_cur, true);
        STEP_TAIL(3, 0, nr_cur, true);
    }

    // ---- final tail epilogue: last tile has parity 1; norms from gmem ----
    {
        float rs_[2][2] = {{0.f, 0.f}, {0.f, 0.f}};
#pragma unroll
        for (int ks_ = 0; ks_ < 8; ks_++) {
            float2 nc_ = __ldg((const float2*)(g_nim + (size_t)bn_prev * 128 +
                                               wn * 64 + ks_ * 8 + t * 2));
            EPI_PAIR(0, ks_, nc_.x, nc_.y, nr_cur);   // acc[1] == acc[1-0]
        }
        EPI_REDUCE_STORE();
    }
}

// ---------------------------------------------------------------------------
// Per-row lse + exact diag, block partial sums; last block finishes the mean.
// All reduction orders fixed -> deterministic.
// ---------------------------------------------------------------------------
__global__ void rows_kernel(float* __restrict__ out, int B, int nt, int out_size) {
    __shared__ float sm[256];
    int i = blockIdx.x * blockDim.x + threadIdx.x;
    float rv = 0.f;
    if (i < B) {
        float s = 0.f;
        const float* p = g_partial + (size_t)i * nt * 2;
        for (int tt = 0; tt < 2 * nt; tt++) s += p[tt];
        rv = logf(s) + g_diag[i];
    }
    sm[threadIdx.x] = rv;
    __syncthreads();
    for (int o = 128; o; o >>= 1) {
        if (threadIdx.x < o) sm[threadIdx.x] += sm[threadIdx.x + o];
        __syncthreads();
    }
    if (threadIdx.x == 0) {
        g_bsum[blockIdx.x] = sm[0];
        __threadfence();
        unsigned done = atomicAdd(&g_cnt, 1u);
        if (done == gridDim.x - 1) {
            float s = 0.f;
            for (unsigned b = 0; b < gridDim.x; b++) s += g_bsum[b];
            float loss = s / (float)B;
            for (int k = 0; k < out_size; k++) out[k] = loss;
            g_cnt = 0u;
        }
    }
}

extern "C" void kernel_launch(void* const* d_in, const int* in_sizes, int n_in,
                              void* d_out, int out_size) {
    const float* sk = (const float*)d_in[0];
    const float* im = (const float*)d_in[1];
    float* out = (float*)d_out;

    int B = in_sizes[0] / DIM;   // 8192
    int nt = B / TILE;           // 64
    int NG = nt * (nt / 4);      // 1024 groups

    prep_kernel<<<dim3(B / 8, 3), 256>>>(sk, im, B);

    int dev = 0, nsm = 148;
    cudaGetDevice(&dev);
    cudaDeviceGetAttribute(&nsm, cudaDevAttrMultiProcessorCount, dev);
    if (nsm < 1) nsm = 148;
    if (nsm > NG) nsm = NG;

    static const int SMEM_BYTES = SMEM_WORDS * 4;   // 143360
    cudaFuncSetAttribute(dist_mma, cudaFuncAttributeMaxDynamicSharedMemorySize, SMEM_BYTES);
    dist_mma<<<nsm, 256, SMEM_BYTES>>>(nt, NG);

    rows_kernel<<<(B + 255) / 256, 256>>>(out, B, nt, out_size);
}

// round 15
// speedup vs baseline: 2.7858x; 1.5199x over previous
#include <cuda_runtime.h>
#include <cuda_fp16.h>
#include <cstdint>
#include <math.h>

#define DIM 128
#define TILE 128
#define BMAX 8192
#define NTMAX 64
#define TPB 4                  // B-tiles per CTA; A tile stays resident
#define LDW 68                 // smem row stride in words (272B): banks (4g+t)%32 distinct

__device__ float g_nsk[BMAX];
__device__ float g_nim[BMAX];
__device__ uint32_t g_skh[BMAX * 64];                     // f16x2-packed rows
__device__ uint32_t g_imh[BMAX * 64];
__device__ float g_partial[(size_t)BMAX * NTMAX * 2];     // per (row, bn, wn-half)
__device__ float g_diag[BMAX];                            // exact fp32 diagonal distance
__device__ float g_bsum[32];
__device__ unsigned g_cnt;

static __device__ __forceinline__ uint32_t s2u(const void* p) {
    uint32_t a;
    asm("{ .reg .u64 t; cvta.to.shared.u64 t, %1; cvt.u32.u64 %0, t; }" : "=r"(a) : "l"(p));
    return a;
}
static __device__ __forceinline__ void cpa16(uint32_t dst, const void* src) {
    asm volatile("cp.async.cg.shared.global [%0], [%1], 16;" :: "r"(dst), "l"(src) : "memory");
}
#define CP_COMMIT() asm volatile("cp.async.commit_group;" ::: "memory")
#define CP_WAIT0()  asm volatile("cp.async.wait_group 0;" ::: "memory")
#define CP_WAIT1()  asm volatile("cp.async.wait_group 1;" ::: "memory")

// f16-accumulate legacy HMMA: 2-reg packed accumulator
static __device__ __forceinline__ void mma16h(uint32_t* c, const uint32_t* a, const uint32_t* b) {
    asm("mma.sync.aligned.m16n8k16.row.col.f16.f16.f16.f16 "
        "{%0,%1}, {%2,%3,%4,%5}, {%6,%7}, {%0,%1};"
        : "+r"(c[0]), "+r"(c[1])
        : "r"(a[0]), "r"(a[1]), "r"(a[2]), "r"(a[3]), "r"(b[0]), "r"(b[1]));
}

// ---------------------------------------------------------------------------
// Single-pass prep: one warp per row reads sk+im once -> both f16 packs,
// both fp32 norms, exact fp32 diagonal. Also resets the completion counter.
// ---------------------------------------------------------------------------
__global__ void prep_kernel(const float* __restrict__ sk,
                            const float* __restrict__ im, int B) {
    if (blockIdx.x == 0 && threadIdx.x == 0) g_cnt = 0u;
    int row = (blockIdx.x * blockDim.x + threadIdx.x) >> 5;
    int lane = threadIdx.x & 31;
    if (row >= B) return;

    float4 a = ((const float4*)(sk + (size_t)row * DIM))[lane];
    float4 b = ((const float4*)(im + (size_t)row * DIM))[lane];

    __half2 ha0 = __floats2half2_rn(a.x, a.y);
    __half2 ha1 = __floats2half2_rn(a.z, a.w);
    g_skh[row * 64 + lane * 2]     = *(uint32_t*)&ha0;
    g_skh[row * 64 + lane * 2 + 1] = *(uint32_t*)&ha1;
    __half2 hb0 = __floats2half2_rn(b.x, b.y);
    __half2 hb1 = __floats2half2_rn(b.z, b.w);
    g_imh[row * 64 + lane * 2]     = *(uint32_t*)&hb0;
    g_imh[row * 64 + lane * 2 + 1] = *(uint32_t*)&hb1;

    float sa = a.x * a.x + a.y * a.y + a.z * a.z + a.w * a.w;
    float sb = b.x * b.x + b.y * b.y + b.z * b.z + b.w * b.w;
    float dx = a.x - b.x, dy = a.y - b.y, dz = a.z - b.z, dw = a.w - b.w;
    float sd = dx * dx + dy * dy + dz * dz + dw * dw;
#pragma unroll
    for (int o = 16; o; o >>= 1) {
        sa += __shfl_xor_sync(0xffffffffu, sa, o);
        sb += __shfl_xor_sync(0xffffffffu, sb, o);
        sd += __shfl_xor_sync(0xffffffffu, sd, o);
    }
    if (lane == 0) {
        g_nsk[row] = sa;
        g_nim[row] = sb;
        g_diag[row] = sqrtf(sd);
    }
}

// ---------------------------------------------------------------------------
// Software-pipelined f16 MMA (f16 accumulate) + fused distance/exp epilogue.
// 8 warps, warp tile 32x64; epilogue of tile t-1 interleaved per k-step.
// Occupancy 2: f16 accs (64 regs) fit the 128-reg cap; co-resident CTA fills
// this CTA's prologue/tail idle slots on the tensor pipe.
// ---------------------------------------------------------------------------
__global__ void __launch_bounds__(256, 2)
dist_mma(int nt) {
    extern __shared__ uint32_t smw[];
    const uint32_t sbase = s2u(smw);
    uint32_t* As = smw;
    const uint32_t NORM_OFF = 3u * 128u * LDW;            // word offset of norm buffer
    float* nsm = (float*)(smw + NORM_OFF);                // 4*128 floats

    const int tid = threadIdx.x;
    const int wid = tid >> 5;
    const int lane = tid & 31;
    const int g = lane >> 2;
    const int t = lane & 3;
    const int wm = wid & 3;        // m-block: 32 rows
    const int wn = wid >> 2;       // n-block: 64 cols

    const int ntg = nt / TPB;
    const int bm = blockIdx.x / ntg;
    const int bn0 = (blockIdx.x % ntg) * TPB;

    // ---- prologue: A, B0, norms (group 0); B1 prefetch (group 1) ----
    {
        const uint32_t* Ag = g_skh + (size_t)bm * TILE * 64;
        const uint32_t* Bg = g_imh + (size_t)bn0 * TILE * 64;
#pragma unroll
        for (int it = 0; it < 8; it++) {
            int c = it * 256 + tid;          // 0..2047 16B-chunks
            int row = c >> 4, ch = c & 15;
            uint32_t doff = (uint32_t)row * 272 + (uint32_t)ch * 16;
            cpa16(sbase + doff, Ag + row * 64 + ch * 4);
            cpa16(sbase + 128 * LDW * 4 + doff, Bg + row * 64 + ch * 4);
        }
        if (tid < 128)
            cpa16(sbase + NORM_OFF * 4 + (uint32_t)tid * 16, g_nim + (size_t)bn0 * TILE + tid * 4);
        CP_COMMIT();
        const uint32_t* Bg1 = g_imh + (size_t)(bn0 + 1) * TILE * 64;
#pragma unroll
        for (int it = 0; it < 8; it++) {
            int c = it * 256 + tid;
            int row = c >> 4, ch = c & 15;
            cpa16(sbase + 2 * 128 * LDW * 4 + (uint32_t)row * 272 + (uint32_t)ch * 16,
                  Bg1 + row * 64 + ch * 4);
        }
        CP_COMMIT();
        CP_WAIT1();
    }
    __syncthreads();

    float nr[2][2];
#pragma unroll
    for (int mt = 0; mt < 2; mt++)
#pragma unroll
        for (int h = 0; h < 2; h++)
            nr[mt][h] = g_nsk[bm * TILE + wm * 32 + mt * 16 + h * 8 + g];

    const int a_base = (wm * 32 + g) * LDW + t;
    const int b_base = (wn * 64 + g) * LDW + t;

    uint32_t acc[2][2][8][2];      // [buf][mt][nb][h]  packed f16x2
    float rs[2][2];

#pragma unroll
    for (int tt = 0; tt <= TPB; tt++) {
        const bool do_main = (tt < TPB);
        const bool do_epi = (tt > 0);
        const int nbuf = tt & 1;
        const int bn_old = bn0 + tt - 1;

        // prefetch B[tt+1] into buffer (tt+1)&1
        if (tt + 1 < TPB) {
            const uint32_t* Bg = g_imh + (size_t)(bn0 + tt + 1) * TILE * 64;
            uint32_t dbuf = sbase + (1 + ((tt + 1) & 1)) * 128 * LDW * 4;
#pragma unroll
            for (int it = 0; it < 8; it++) {
                int c = it * 256 + tid;
                int row = c >> 4, ch = c & 15;
                cpa16(dbuf + (uint32_t)row * 272 + (uint32_t)ch * 16, Bg + row * 64 + ch * 4);
            }
            CP_COMMIT();
        }

        uint32_t (*accN)[8][2] = acc[nbuf];
        uint32_t (*accO)[8][2] = acc[nbuf ^ 1];
        const uint32_t* Bs = smw + (1 + (tt & 1)) * 128 * LDW;

        if (do_main) {
#pragma unroll
            for (int mt = 0; mt < 2; mt++)
#pragma unroll
                for (int nb = 0; nb < 8; nb++) {
                    accN[mt][nb][0] = 0u;
                    accN[mt][nb][1] = 0u;
                }
        }
        if (do_epi) { rs[0][0] = rs[0][1] = rs[1][0] = rs[1][1] = 0.f; }

        // 8 k-steps of 16; 1 epilogue chunk (nb=ks) of the previous tile per step
#pragma unroll
        for (int ks = 0; ks < 8; ks++) {
            if (do_main) {
                const int ko = ks * 8;       // 16 f16 = 8 words
                uint32_t a[2][4], b[8][2];
#pragma unroll
                for (int mt = 0; mt < 2; mt++) {
                    int ba = a_base + mt * 16 * LDW + ko;
                    a[mt][0] = As[ba];
                    a[mt][1] = As[ba + 8 * LDW];
                    a[mt][2] = As[ba + 4];
                    a[mt][3] = As[ba + 8 * LDW + 4];
                }
#pragma unroll
                for (int nb = 0; nb < 8; nb++) {
                    int bb = b_base + nb * 8 * LDW + ko;
                    b[nb][0] = Bs[bb];
                    b[nb][1] = Bs[bb + 4];
                }
#pragma unroll
                for (int mt = 0; mt < 2; mt++)
#pragma unroll
                    for (int nb = 0; nb < 8; nb++) mma16h(accN[mt][nb], a[mt], b[nb]);
            }
            if (do_epi) {
                float2 nc = *(const float2*)&nsm[(tt - 1) * 128 + wn * 64 + ks * 8 + t * 2];
#pragma unroll
                for (int mt = 0; mt < 2; mt++) {
#pragma unroll
                    for (int h = 0; h < 2; h++) {
                        float2 dot = __half22float2(*(__half2*)&accO[mt][ks][h]);
                        float base = nr[mt][h];
                        float sq0 = fmaxf(fmaf(-2.f, dot.x, base + nc.x), 0.f);
                        float sq1 = fmaxf(fmaf(-2.f, dot.y, base + nc.y), 0.f);
                        float d0, d1, e0, e1;
                        asm("sqrt.approx.f32 %0, %1;" : "=f"(d0) : "f"(sq0));
                        asm("sqrt.approx.f32 %0, %1;" : "=f"(d1) : "f"(sq1));
                        asm("ex2.approx.f32 %0, %1;" : "=f"(e0) : "f"(d0 * -1.4426950408889634f));
                        asm("ex2.approx.f32 %0, %1;" : "=f"(e1) : "f"(d1 * -1.4426950408889634f));
                        rs[mt][h] += e0 + e1;
                    }
                }
            }
        }

        if (do_epi) {
#pragma unroll
            for (int mt = 0; mt < 2; mt++) {
#pragma unroll
                for (int h = 0; h < 2; h++) {
                    float v = rs[mt][h];
                    v += __shfl_xor_sync(0xffffffffu, v, 1);
                    v += __shfl_xor_sync(0xffffffffu, v, 2);
                    if (t == 0) {
                        int r_local = wm * 32 + mt * 16 + h * 8 + g;
                        g_partial[((size_t)(bm * TILE + r_local) * nt + bn_old) * 2 + wn] = v;
                    }
                }
            }
        }

        if (do_main) {
            CP_WAIT0();
            __syncthreads();
        }
    }
}

// ---------------------------------------------------------------------------
// Per-row lse + exact diag, block partial sums; last block finishes the mean.
// All reduction orders fixed -> deterministic.
// ---------------------------------------------------------------------------
__global__ void rows_kernel(float* __restrict__ out, int B, int nt, int out_size) {
    __shared__ float sm[256];
    int i = blockIdx.x * blockDim.x + threadIdx.x;
    float rv = 0.f;
    if (i < B) {
        float s = 0.f;
        const float* p = g_partial + (size_t)i * nt * 2;
        for (int tt = 0; tt < 2 * nt; tt++) s += p[tt];
        rv = logf(s) + g_diag[i];
    }
    sm[threadIdx.x] = rv;
    __syncthreads();
    for (int o = 128; o; o >>= 1) {
        if (threadIdx.x < o) sm[threadIdx.x] += sm[threadIdx.x + o];
        __syncthreads();
    }
    if (threadIdx.x == 0) {
        g_bsum[blockIdx.x] = sm[0];
        __threadfence();
        unsigned done = atomicAdd(&g_cnt, 1u);
        if (done == gridDim.x - 1) {
            float s = 0.f;
            for (unsigned b = 0; b < gridDim.x; b++) s += g_bsum[b];
            float loss = s / (float)B;
            for (int k = 0; k < out_size; k++) out[k] = loss;
            g_cnt = 0u;
        }
    }
}

extern "C" void kernel_launch(void* const* d_in, const int* in_sizes, int n_in,
                              void* d_out, int out_size) {
    const float* sk = (const float*)d_in[0];
    const float* im = (const float*)d_in[1];
    float* out = (float*)d_out;

    int B = in_sizes[0] / DIM;   // 8192
    int nt = B / TILE;           // 64

    prep_kernel<<<B / 8, 256>>>(sk, im, B);

    static const int SMEM_BYTES = (3 * 128 * LDW + 4 * 128) * 4;   // 106496
    cudaFuncSetAttribute(dist_mma, cudaFuncAttributeMaxDynamicSharedMemorySize, SMEM_BYTES);
    int ncta = nt * (nt / TPB);  // 1024
    dist_mma<<<ncta, 256, SMEM_BYTES>>>(nt);

    rows_kernel<<<(B + 255) / 256, 256>>>(out, B, nt, out_size);
}

// round 16
// speedup vs baseline: 2.7895x; 1.0013x over previous
#include <cuda_runtime.h>
#include <cuda_fp16.h>
#include <cstdint>
#include <math.h>

#define DIM 128
#define TILE 128
#define BMAX 8192
#define NTMAX 64
#define TPB 4                  // B-tiles per CTA; A tile stays resident
#define LDW 68                 // smem row stride in words (272B): banks (4g+t)%32 distinct

__device__ float g_nsk[BMAX];
__device__ float g_nim[BMAX];
__device__ uint32_t g_skh[BMAX * 64];                     // f16x2-packed rows
__device__ uint32_t g_imh[BMAX * 64];
__device__ float g_partial[(size_t)BMAX * NTMAX * 2];     // per (row, bn, wn-half)
__device__ float g_diag[BMAX];                            // exact fp32 diagonal distance
__device__ float g_bsum[NTMAX];                           // per-bm row-block sums
__device__ unsigned g_cnt_bm[NTMAX];                      // per-bm completion counters
__device__ unsigned g_cnt2;                               // bm-winner counter

static __device__ __forceinline__ uint32_t s2u(const void* p) {
    uint32_t a;
    asm("{ .reg .u64 t; cvta.to.shared.u64 t, %1; cvt.u32.u64 %0, t; }" : "=r"(a) : "l"(p));
    return a;
}
static __device__ __forceinline__ void cpa16(uint32_t dst, const void* src) {
    asm volatile("cp.async.cg.shared.global [%0], [%1], 16;" :: "r"(dst), "l"(src) : "memory");
}
#define CP_COMMIT() asm volatile("cp.async.commit_group;" ::: "memory")
#define CP_WAIT0()  asm volatile("cp.async.wait_group 0;" ::: "memory")
#define CP_WAIT1()  asm volatile("cp.async.wait_group 1;" ::: "memory")

// f16-accumulate legacy HMMA: 2-reg packed accumulator
static __device__ __forceinline__ void mma16h(uint32_t* c, const uint32_t* a, const uint32_t* b) {
    asm("mma.sync.aligned.m16n8k16.row.col.f16.f16.f16.f16 "
        "{%0,%1}, {%2,%3,%4,%5}, {%6,%7}, {%0,%1};"
        : "+r"(c[0]), "+r"(c[1])
        : "r"(a[0]), "r"(a[1]), "r"(a[2]), "r"(a[3]), "r"(b[0]), "r"(b[1]));
}

// ---------------------------------------------------------------------------
// Single-pass prep: one warp per row reads sk+im once -> both f16 packs,
// both fp32 norms, exact fp32 diagonal. Also resets completion counters.
// ---------------------------------------------------------------------------
__global__ void prep_kernel(const float* __restrict__ sk,
                            const float* __restrict__ im, int B) {
    if (blockIdx.x == 0) {
        if (threadIdx.x < NTMAX) g_cnt_bm[threadIdx.x] = 0u;
        if (threadIdx.x == NTMAX) g_cnt2 = 0u;
    }
    int row = (blockIdx.x * blockDim.x + threadIdx.x) >> 5;
    int lane = threadIdx.x & 31;
    if (row >= B) return;

    float4 a = ((const float4*)(sk + (size_t)row * DIM))[lane];
    float4 b = ((const float4*)(im + (size_t)row * DIM))[lane];

    __half2 ha0 = __floats2half2_rn(a.x, a.y);
    __half2 ha1 = __floats2half2_rn(a.z, a.w);
    g_skh[row * 64 + lane * 2]     = *(uint32_t*)&ha0;
    g_skh[row * 64 + lane * 2 + 1] = *(uint32_t*)&ha1;
    __half2 hb0 = __floats2half2_rn(b.x, b.y);
    __half2 hb1 = __floats2half2_rn(b.z, b.w);
    g_imh[row * 64 + lane * 2]     = *(uint32_t*)&hb0;
    g_imh[row * 64 + lane * 2 + 1] = *(uint32_t*)&hb1;

    float sa = a.x * a.x + a.y * a.y + a.z * a.z + a.w * a.w;
    float sb = b.x * b.x + b.y * b.y + b.z * b.z + b.w * b.w;
    float dx = a.x - b.x, dy = a.y - b.y, dz = a.z - b.z, dw = a.w - b.w;
    float sd = dx * dx + dy * dy + dz * dz + dw * dw;
#pragma unroll
    for (int o = 16; o; o >>= 1) {
        sa += __shfl_xor_sync(0xffffffffu, sa, o);
        sb += __shfl_xor_sync(0xffffffffu, sb, o);
        sd += __shfl_xor_sync(0xffffffffu, sd, o);
    }
    if (lane == 0) {
        g_nsk[row] = sa;
        g_nim[row] = sb;
        g_diag[row] = sqrtf(sd);
    }
}

// ---------------------------------------------------------------------------
// Software-pipelined f16 MMA (f16 accumulate) + fused distance/exp epilogue.
// 8 warps, warp tile 32x64; epilogue of tile t-1 interleaved per k-step.
// Occupancy 2. Tail: per-bm last-CTA election reduces its 128 rows (fixed
// order), last bm-winner does the final 64-way sum. No extra launches.
// ---------------------------------------------------------------------------
__global__ void __launch_bounds__(256, 2)
dist_mma(float* __restrict__ out, int nt, int out_size) {
    extern __shared__ uint32_t smw[];
    const uint32_t sbase = s2u(smw);
    uint32_t* As = smw;
    const uint32_t NORM_OFF = 3u * 128u * LDW;            // word offset of norm buffer
    float* nsm = (float*)(smw + NORM_OFF);                // 4*128 floats
    __shared__ unsigned s_rank;

    const int tid = threadIdx.x;
    const int wid = tid >> 5;
    const int lane = tid & 31;
    const int g = lane >> 2;
    const int t = lane & 3;
    const int wm = wid & 3;        // m-block: 32 rows
    const int wn = wid >> 2;       // n-block: 64 cols

    const int ntg = nt / TPB;
    const int bm = blockIdx.x / ntg;
    const int bn0 = (blockIdx.x % ntg) * TPB;

    // ---- prologue: A, B0, norms (group 0); B1 prefetch (group 1) ----
    {
        const uint32_t* Ag = g_skh + (size_t)bm * TILE * 64;
        const uint32_t* Bg = g_imh + (size_t)bn0 * TILE * 64;
#pragma unroll
        for (int it = 0; it < 8; it++) {
            int c = it * 256 + tid;          // 0..2047 16B-chunks
            int row = c >> 4, ch = c & 15;
            uint32_t doff = (uint32_t)row * 272 + (uint32_t)ch * 16;
            cpa16(sbase + doff, Ag + row * 64 + ch * 4);
            cpa16(sbase + 128 * LDW * 4 + doff, Bg + row * 64 + ch * 4);
        }
        if (tid < 128)
            cpa16(sbase + NORM_OFF * 4 + (uint32_t)tid * 16, g_nim + (size_t)bn0 * TILE + tid * 4);
        CP_COMMIT();
        const uint32_t* Bg1 = g_imh + (size_t)(bn0 + 1) * TILE * 64;
#pragma unroll
        for (int it = 0; it < 8; it++) {
            int c = it * 256 + tid;
            int row = c >> 4, ch = c & 15;
            cpa16(sbase + 2 * 128 * LDW * 4 + (uint32_t)row * 272 + (uint32_t)ch * 16,
                  Bg1 + row * 64 + ch * 4);
        }
        CP_COMMIT();
        CP_WAIT1();
    }
    __syncthreads();

    float nr[2][2];
#pragma unroll
    for (int mt = 0; mt < 2; mt++)
#pragma unroll
        for (int h = 0; h < 2; h++)
            nr[mt][h] = g_nsk[bm * TILE + wm * 32 + mt * 16 + h * 8 + g];

    const int a_base = (wm * 32 + g) * LDW + t;
    const int b_base = (wn * 64 + g) * LDW + t;

    uint32_t acc[2][2][8][2];      // [buf][mt][nb][h]  packed f16x2
    float rs[2][2];

#pragma unroll
    for (int tt = 0; tt <= TPB; tt++) {
        const bool do_main = (tt < TPB);
        const bool do_epi = (tt > 0);
        const int nbuf = tt & 1;
        const int bn_old = bn0 + tt - 1;

        // prefetch B[tt+1] into buffer (tt+1)&1
        if (tt + 1 < TPB) {
            const uint32_t* Bg = g_imh + (size_t)(bn0 + tt + 1) * TILE * 64;
            uint32_t dbuf = sbase + (1 + ((tt + 1) & 1)) * 128 * LDW * 4;
#pragma unroll
            for (int it = 0; it < 8; it++) {
                int c = it * 256 + tid;
                int row = c >> 4, ch = c & 15;
                cpa16(dbuf + (uint32_t)row * 272 + (uint32_t)ch * 16, Bg + row * 64 + ch * 4);
            }
            CP_COMMIT();
        }

        uint32_t (*accN)[8][2] = acc[nbuf];
        uint32_t (*accO)[8][2] = acc[nbuf ^ 1];
        const uint32_t* Bs = smw + (1 + (tt & 1)) * 128 * LDW;

        if (do_main) {
#pragma unroll
            for (int mt = 0; mt < 2; mt++)
#pragma unroll
                for (int nb = 0; nb < 8; nb++) {
                    accN[mt][nb][0] = 0u;
                    accN[mt][nb][1] = 0u;
                }
        }
        if (do_epi) { rs[0][0] = rs[0][1] = rs[1][0] = rs[1][1] = 0.f; }

        // 8 k-steps of 16; 1 epilogue chunk (nb=ks) of the previous tile per step
#pragma unroll
        for (int ks = 0; ks < 8; ks++) {
            if (do_main) {
                const int ko = ks * 8;       // 16 f16 = 8 words
                uint32_t a[2][4], b[8][2];
#pragma unroll
                for (int mt = 0; mt < 2; mt++) {
                    int ba = a_base + mt * 16 * LDW + ko;
                    a[mt][0] = As[ba];
                    a[mt][1] = As[ba + 8 * LDW];
                    a[mt][2] = As[ba + 4];
                    a[mt][3] = As[ba + 8 * LDW + 4];
                }
#pragma unroll
                for (int nb = 0; nb < 8; nb++) {
                    int bb = b_base + nb * 8 * LDW + ko;
                    b[nb][0] = Bs[bb];
                    b[nb][1] = Bs[bb + 4];
                }
#pragma unroll
                for (int mt = 0; mt < 2; mt++)
#pragma unroll
                    for (int nb = 0; nb < 8; nb++) mma16h(accN[mt][nb], a[mt], b[nb]);
            }
            if (do_epi) {
                float2 nc = *(const float2*)&nsm[(tt - 1) * 128 + wn * 64 + ks * 8 + t * 2];
#pragma unroll
                for (int mt = 0; mt < 2; mt++) {
#pragma unroll
                    for (int h = 0; h < 2; h++) {
                        float2 dot = __half22float2(*(__half2*)&accO[mt][ks][h]);
                        float base = nr[mt][h];
                        float sq0 = fmaxf(fmaf(-2.f, dot.x, base + nc.x), 0.f);
                        float sq1 = fmaxf(fmaf(-2.f, dot.y, base + nc.y), 0.f);
                        float d0, d1, e0, e1;
                        asm("sqrt.approx.f32 %0, %1;" : "=f"(d0) : "f"(sq0));
                        asm("sqrt.approx.f32 %0, %1;" : "=f"(d1) : "f"(sq1));
                        asm("ex2.approx.f32 %0, %1;" : "=f"(e0) : "f"(d0 * -1.4426950408889634f));
                        asm("ex2.approx.f32 %0, %1;" : "=f"(e1) : "f"(d1 * -1.4426950408889634f));
                        rs[mt][h] += e0 + e1;
                    }
                }
            }
        }

        if (do_epi) {
#pragma unroll
            for (int mt = 0; mt < 2; mt++) {
#pragma unroll
                for (int h = 0; h < 2; h++) {
                    float v = rs[mt][h];
                    v += __shfl_xor_sync(0xffffffffu, v, 1);
                    v += __shfl_xor_sync(0xffffffffu, v, 2);
                    if (t == 0) {
                        int r_local = wm * 32 + mt * 16 + h * 8 + g;
                        g_partial[((size_t)(bm * TILE + r_local) * nt + bn_old) * 2 + wn] = v;
                    }
                }
            }
        }

        if (do_main) {
            CP_WAIT0();
            __syncthreads();
        }
    }

    // ---- fused reduction tail ----
    // Election: 16th CTA of this bm reduces its 128 rows (fixed order).
    __threadfence();
    __syncthreads();
    if (tid == 0) s_rank = atomicAdd(&g_cnt_bm[bm], 1u);
    __syncthreads();
    if (s_rank == (unsigned)(ntg - 1)) {
        float rv = 0.f;
        if (tid < TILE) {
            int row = bm * TILE + tid;
            const float* p = g_partial + (size_t)row * nt * 2;
            float s = 0.f;
            for (int k = 0; k < 2 * nt; k++) s += p[k];   // fixed order
            rv = logf(s) + g_diag[row];
        }
        float* red = (float*)smw;    // reuse dynamic smem
        red[tid] = rv;
        __syncthreads();
        for (int o = 128; o; o >>= 1) {
            if (tid < o) red[tid] += red[tid + o];
            __syncthreads();
        }
        if (tid == 0) {
            g_bsum[bm] = red[0];
            __threadfence();
            unsigned done = atomicAdd(&g_cnt2, 1u);
            if (done == (unsigned)(nt - 1)) {
                float s = 0.f;
                for (int b = 0; b < nt; b++) s += g_bsum[b];   // fixed order
                float loss = s / (float)(nt * TILE);
                for (int k = 0; k < out_size; k++) out[k] = loss;
            }
        }
    }
}

extern "C" void kernel_launch(void* const* d_in, const int* in_sizes, int n_in,
                              void* d_out, int out_size) {
    const float* sk = (const float*)d_in[0];
    const float* im = (const float*)d_in[1];
    float* out = (float*)d_out;

    int B = in_sizes[0] / DIM;   // 8192
    int nt = B / TILE;           // 64

    prep_kernel<<<B / 8, 256>>>(sk, im, B);

    static const int SMEM_BYTES = (3 * 128 * LDW + 4 * 128) * 4;   // 106496
    cudaFuncSetAttribute(dist_mma, cudaFuncAttributeMaxDynamicSharedMemorySize, SMEM_BYTES);
    int ncta = nt * (nt / TPB);  // 1024
    dist_mma<<<ncta, 256, SMEM_BYTES>>>(out, nt, out_size);
}